// round 1
// baseline (speedup 1.0000x reference)
#include <cuda_runtime.h>
#include <cuda_bf16.h>
#include <math.h>

// Problem constants (fixed shapes for this problem instance)
#define FEAT   240
#define NG     1000
#define MAXN   400000
#define NINST  112   // 64 (l=0) + 32 (l=1) + 16 (l=2)

// Scratch (no cudaMalloc allowed)
__device__ int g_cnt[NG];
__device__ int g_off[NG];
__device__ int g_cur[NG];
__device__ int g_perm[MAXN];

__global__ void k_zero()
{
    int i = blockIdx.x * blockDim.x + threadIdx.x;
    if (i < NG) g_cnt[i] = 0;
}

__global__ void k_hist(const int* __restrict__ idx, int n)
{
    int i = blockIdx.x * blockDim.x + threadIdx.x;
    if (i < n) atomicAdd(&g_cnt[idx[i]], 1);
}

// Single-block exclusive scan over NG (<=1024) counters.
__global__ void k_scan()
{
    __shared__ int s[1024];
    int t = threadIdx.x;
    int v = (t < NG) ? g_cnt[t] : 0;
    s[t] = v;
    __syncthreads();
#pragma unroll
    for (int o = 1; o < 1024; o <<= 1) {
        int w = (t >= o) ? s[t - o] : 0;
        __syncthreads();
        s[t] += w;
        __syncthreads();
    }
    if (t < NG) {
        int ex = s[t] - v;   // exclusive prefix
        g_off[t] = ex;
        g_cur[t] = ex;
    }
}

__global__ void k_scatter(const int* __restrict__ idx, int n)
{
    int i = blockIdx.x * blockDim.x + threadIdx.x;
    if (i < n) {
        int g = idx[i];
        int p = atomicAdd(&g_cur[g], 1);
        g_perm[p] = i;
    }
}

// One block per graph. 128 threads; threads 0..111 each own one irrep instance.
// Register accumulators: mean-sum, exp(+norm)-weighted sum, exp(-norm)-weighted
// sum (d components each) + the two exp partition sums. Then the tiny per-irrep
// linear layers are applied from shared memory and written out.
__global__ __launch_bounds__(128) void k_main(
    const float* __restrict__ x,
    const float* __restrict__ W0,
    const float* __restrict__ W1,
    const float* __restrict__ W2,
    const float* __restrict__ b0,
    float* __restrict__ out)
{
    const int g = blockIdx.x;
    const int t = threadIdx.x;
    const int start = g_off[g];
    const int cnt   = g_cnt[g];

    // instance -> (d, feature base)
    int d = 0, base = 0;
    const bool active = (t < NINST);
    if (t < 64)       { d = 1; base = t; }
    else if (t < 96)  { d = 3; base = 64 + (t - 64) * 3; }
    else if (t < 112) { d = 5; base = 160 + (t - 96) * 5; }

    float aS[5] = {0.f, 0.f, 0.f, 0.f, 0.f};   // plain sum (mean)
    float aX[5] = {0.f, 0.f, 0.f, 0.f, 0.f};   // exp(+norm) weighted
    float aN[5] = {0.f, 0.f, 0.f, 0.f, 0.f};   // exp(-norm) weighted
    float zx = 0.f, zn = 0.f;

    if (active) {
#pragma unroll 4
        for (int i = 0; i < cnt; i++) {
            int node = g_perm[start + i];
            const float* row = x + (size_t)node * FEAT + base;
            float v[5];
#pragma unroll
            for (int j = 0; j < 5; j++) if (j < d) v[j] = row[j];
            float sq = 0.f;
#pragma unroll
            for (int j = 0; j < 5; j++) if (j < d) sq = fmaf(v[j], v[j], sq);
            float nr = sqrtf(sq);
            float ex = __expf(nr);
            float en = __expf(-nr);
            zx += ex;
            zn += en;
#pragma unroll
            for (int j = 0; j < 5; j++) if (j < d) {
                aS[j] += v[j];
                aX[j] = fmaf(v[j], ex, aX[j]);
                aN[j] = fmaf(v[j], en, aN[j]);
            }
        }
    }

    __shared__ float shm[FEAT];  // mean pooled
    __shared__ float shx[FEAT];  // softmax pooled
    __shared__ float shn[FEAT];  // softmin pooled

    if (active) {
        float cinv = 1.0f / fmaxf((float)cnt, 1.0f);
        float ix = (zx > 0.f) ? (1.0f / zx) : 0.f;
        float in_ = (zn > 0.f) ? (1.0f / zn) : 0.f;
#pragma unroll
        for (int j = 0; j < 5; j++) if (j < d) {
            shm[base + j] = aS[j] * cinv;
            shx[base + j] = aX[j] * ix;
            shn[base + j] = aN[j] * in_;
        }
    }
    __syncthreads();

    // Linear phase: out[o,dd] = (sum_i cat[i,dd] * W[i,o]) / sqrt(3*mul) (+ b0)
    // cat = [mean ; max ; min] along i.
    for (int e = t; e < FEAT; e += blockDim.x) {
        int mul, st, o, dd, dl;
        const float* W;
        float scale, bias = 0.f;
        if (e < 64) {
            mul = 64; st = 0;   o = e;              dd = 0;            dl = 1;
            W = W0; scale = 0.07216878364870323f;   // 1/sqrt(192)
            bias = b0[o];
        } else if (e < 160) {
            int r = e - 64;
            mul = 32; st = 64;  o = r / 3;          dd = r - 3 * o;    dl = 3;
            W = W1; scale = 0.10206207261596575f;   // 1/sqrt(96)
        } else {
            int r = e - 160;
            mul = 16; st = 160; o = r / 5;          dd = r - 5 * o;    dl = 5;
            W = W2; scale = 0.14433756729740643f;   // 1/sqrt(48)
        }
        float acc = 0.f;
        for (int i = 0; i < mul; i++)
            acc = fmaf(shm[st + i * dl + dd], W[i * mul + o], acc);
        for (int i = 0; i < mul; i++)
            acc = fmaf(shx[st + i * dl + dd], W[(mul + i) * mul + o], acc);
        for (int i = 0; i < mul; i++)
            acc = fmaf(shn[st + i * dl + dd], W[(2 * mul + i) * mul + o], acc);
        out[(size_t)g * FEAT + e] = fmaf(acc, scale, bias);
    }
}

extern "C" void kernel_launch(void* const* d_in, const int* in_sizes, int n_in,
                              void* d_out, int out_size)
{
    const float* x   = (const float*)d_in[0];
    const int*   idx = (const int*)d_in[1];
    // d_in[2] = dim_size (scalar, fixed at 1000 for this problem)
    const float* W0  = (const float*)d_in[3];
    const float* W1  = (const float*)d_in[4];
    const float* W2  = (const float*)d_in[5];
    const float* b0  = (const float*)d_in[6];
    float* out = (float*)d_out;

    int n = in_sizes[0] / FEAT;   // number of nodes

    k_zero<<<(NG + 255) / 256, 256>>>();
    k_hist<<<(n + 255) / 256, 256>>>(idx, n);
    k_scan<<<1, 1024>>>();
    k_scatter<<<(n + 255) / 256, 256>>>(idx, n);
    k_main<<<NG, 128>>>(x, W0, W1, W2, b0, out);
}

// round 2
// speedup vs baseline: 1.0626x; 1.0626x over previous
#include <cuda_runtime.h>
#include <cuda_bf16.h>
#include <math.h>

// Problem constants (fixed shapes for this problem instance)
#define FEAT   240
#define NG     1000
#define MAXN   400000
#define NINST  112   // 64 (l=0) + 32 (l=1) + 16 (l=2)
#define SPLIT  8     // slices per graph in the accumulation phase
#define PW     960   // padded width of one partial record (floats)

// Scratch (no cudaMalloc allowed)
__device__ int   g_cnt[NG];
__device__ int   g_off[NG];
__device__ int   g_cur[NG];
__device__ int   g_perm[MAXN];
__device__ float g_part[(size_t)NG * SPLIT * PW];   // ~30.7 MB

__global__ void k_zero()
{
    int i = blockIdx.x * blockDim.x + threadIdx.x;
    if (i < NG) g_cnt[i] = 0;
}

__global__ void k_hist(const int* __restrict__ idx, int n)
{
    int i = blockIdx.x * blockDim.x + threadIdx.x;
    if (i < n) atomicAdd(&g_cnt[idx[i]], 1);
}

// Single-block exclusive scan over NG (<=1024) counters.
__global__ void k_scan()
{
    __shared__ int s[1024];
    int t = threadIdx.x;
    int v = (t < NG) ? g_cnt[t] : 0;
    s[t] = v;
    __syncthreads();
#pragma unroll
    for (int o = 1; o < 1024; o <<= 1) {
        int w = (t >= o) ? s[t - o] : 0;
        __syncthreads();
        s[t] += w;
        __syncthreads();
    }
    if (t < NG) {
        int ex = s[t] - v;   // exclusive prefix
        g_off[t] = ex;
        g_cur[t] = ex;
    }
}

__global__ void k_scatter(const int* __restrict__ idx, int n)
{
    int i = blockIdx.x * blockDim.x + threadIdx.x;
    if (i < n) {
        int g = idx[i];
        int p = atomicAdd(&g_cur[g], 1);
        g_perm[p] = i;
    }
}

// Phase A: grid (NG, SPLIT). Each block accumulates one slice of one graph's
// nodes into register accumulators, then dumps partials to g_part.
// Threads 0..111 each own one irrep instance.
__global__ __launch_bounds__(128) void k_accum(const float* __restrict__ x)
{
    const int g = blockIdx.x;
    const int s = blockIdx.y;
    const int t = threadIdx.x;
    const int start = g_off[g];
    const int cnt   = g_cnt[g];
    const int per = (cnt + SPLIT - 1) / SPLIT;
    const int i0 = s * per;
    const int i1 = min(cnt, i0 + per);

    // instance -> (d, feature base)
    int d = 0, base = 0;
    const bool active = (t < NINST);
    if (t < 64)       { d = 1; base = t; }
    else if (t < 96)  { d = 3; base = 64 + (t - 64) * 3; }
    else if (t < 112) { d = 5; base = 160 + (t - 96) * 5; }

    float aS[5] = {0.f, 0.f, 0.f, 0.f, 0.f};   // plain sum (mean numerator)
    float aX[5] = {0.f, 0.f, 0.f, 0.f, 0.f};   // exp(+norm) weighted
    float aN[5] = {0.f, 0.f, 0.f, 0.f, 0.f};   // exp(-norm) weighted
    float zx = 0.f, zn = 0.f;

    if (active) {
#pragma unroll 4
        for (int i = i0; i < i1; i++) {
            int node = g_perm[start + i];
            const float* row = x + (size_t)node * FEAT + base;
            float v[5];
#pragma unroll
            for (int j = 0; j < 5; j++) if (j < d) v[j] = row[j];
            float sq = 0.f;
#pragma unroll
            for (int j = 0; j < 5; j++) if (j < d) sq = fmaf(v[j], v[j], sq);
            float nr = sqrtf(sq);
            float ex = __expf(nr);
            float en = __expf(-nr);
            zx += ex;
            zn += en;
#pragma unroll
            for (int j = 0; j < 5; j++) if (j < d) {
                aS[j] += v[j];
                aX[j] = fmaf(v[j], ex, aX[j]);
                aN[j] = fmaf(v[j], en, aN[j]);
            }
        }
    }

    float* p = g_part + ((size_t)g * SPLIT + s) * PW;
    if (active) {
#pragma unroll
        for (int j = 0; j < 5; j++) if (j < d) {
            p[base + j]       = aS[j];
            p[240 + base + j] = aX[j];
            p[480 + base + j] = aN[j];
        }
        p[720 + t] = zx;
        p[832 + t] = zn;
    }
}

// Phase B: one block per graph. Reduce the SPLIT partials, normalize, then
// apply the fused per-irrep linear layers and write the output row.
__global__ __launch_bounds__(128) void k_combine(
    const float* __restrict__ W0,
    const float* __restrict__ W1,
    const float* __restrict__ W2,
    const float* __restrict__ b0,
    float* __restrict__ out)
{
    const int g = blockIdx.x;
    const int t = threadIdx.x;
    const int cnt = g_cnt[g];

    int d = 0, base = 0;
    const bool active = (t < NINST);
    if (t < 64)       { d = 1; base = t; }
    else if (t < 96)  { d = 3; base = 64 + (t - 64) * 3; }
    else if (t < 112) { d = 5; base = 160 + (t - 96) * 5; }

    float aS[5] = {0.f, 0.f, 0.f, 0.f, 0.f};
    float aX[5] = {0.f, 0.f, 0.f, 0.f, 0.f};
    float aN[5] = {0.f, 0.f, 0.f, 0.f, 0.f};
    float zx = 0.f, zn = 0.f;

    if (active) {
        const float* pg = g_part + (size_t)g * SPLIT * PW;
#pragma unroll
        for (int s = 0; s < SPLIT; s++) {
            const float* p = pg + (size_t)s * PW;
#pragma unroll
            for (int j = 0; j < 5; j++) if (j < d) {
                aS[j] += p[base + j];
                aX[j] += p[240 + base + j];
                aN[j] += p[480 + base + j];
            }
            zx += p[720 + t];
            zn += p[832 + t];
        }
    }

    __shared__ float shm[FEAT];  // mean pooled
    __shared__ float shx[FEAT];  // softmax pooled
    __shared__ float shn[FEAT];  // softmin pooled

    if (active) {
        float cinv = 1.0f / fmaxf((float)cnt, 1.0f);
        float ix  = (zx > 0.f) ? (1.0f / zx) : 0.f;
        float in_ = (zn > 0.f) ? (1.0f / zn) : 0.f;
#pragma unroll
        for (int j = 0; j < 5; j++) if (j < d) {
            shm[base + j] = aS[j] * cinv;
            shx[base + j] = aX[j] * ix;
            shn[base + j] = aN[j] * in_;
        }
    }
    __syncthreads();

    // Linear phase: out[o,dd] = (sum_i cat[i,dd] * W[i,o]) / sqrt(3*mul) (+ b0)
    for (int e = t; e < FEAT; e += blockDim.x) {
        int mul, st, o, dd, dl;
        const float* W;
        float scale, bias = 0.f;
        if (e < 64) {
            mul = 64; st = 0;   o = e;            dd = 0;         dl = 1;
            W = W0; scale = 0.07216878364870323f;   // 1/sqrt(192)
            bias = b0[o];
        } else if (e < 160) {
            int r = e - 64;
            mul = 32; st = 64;  o = r / 3;        dd = r - 3 * o; dl = 3;
            W = W1; scale = 0.10206207261596575f;   // 1/sqrt(96)
        } else {
            int r = e - 160;
            mul = 16; st = 160; o = r / 5;        dd = r - 5 * o; dl = 5;
            W = W2; scale = 0.14433756729740643f;   // 1/sqrt(48)
        }
        float acc = 0.f;
        for (int i = 0; i < mul; i++)
            acc = fmaf(shm[st + i * dl + dd], W[i * mul + o], acc);
        for (int i = 0; i < mul; i++)
            acc = fmaf(shx[st + i * dl + dd], W[(mul + i) * mul + o], acc);
        for (int i = 0; i < mul; i++)
            acc = fmaf(shn[st + i * dl + dd], W[(2 * mul + i) * mul + o], acc);
        out[(size_t)g * FEAT + e] = fmaf(acc, scale, bias);
    }
}

extern "C" void kernel_launch(void* const* d_in, const int* in_sizes, int n_in,
                              void* d_out, int out_size)
{
    const float* x   = (const float*)d_in[0];
    const int*   idx = (const int*)d_in[1];
    // d_in[2] = dim_size (scalar, fixed at 1000 for this problem)
    const float* W0  = (const float*)d_in[3];
    const float* W1  = (const float*)d_in[4];
    const float* W2  = (const float*)d_in[5];
    const float* b0  = (const float*)d_in[6];
    float* out = (float*)d_out;

    int n = in_sizes[0] / FEAT;   // number of nodes

    k_zero<<<(NG + 255) / 256, 256>>>();
    k_hist<<<(n + 255) / 256, 256>>>(idx, n);
    k_scan<<<1, 1024>>>();
    k_scatter<<<(n + 255) / 256, 256>>>(idx, n);
    dim3 ga(NG, SPLIT);
    k_accum<<<ga, 128>>>(x);
    k_combine<<<NG, 128>>>(W0, W1, W2, b0, out);
}